// round 16
// baseline (speedup 1.0000x reference)
#include <cuda_runtime.h>
#include <math.h>

#define NQ   12
#define DIM  4096
#define NL   4
#define TPB  256

__device__ __forceinline__ float2 cmul(float2 a, float2 b) {
    return make_float2(a.x * b.x - a.y * b.y, a.x * b.y + a.y * b.x);
}

// Phase-normalized fused RZ*RY*RX gate per (layer, wire): M = phi*U,
// phi = conj(u00)/|u00|, U in SU(2). M = diag(1, phi^2) * M'' with
// M'' = [[c, b], [-conj(b), c]], c real (12-FFMA form). Deferred diagonals:
// folded into 14-form (HIGH gates, layers 1-2), accumulated into per-thread
// lo_n[t] (MID/LOW wires, layers 1-2) folded into the position-8 HIGH gate
// (16-FFMA form), or dropped (layer 3: dead phases). The layer-3 position-8
// gate is fused into the epilogue quadratic form (P/M computed directly from
// pre-gate amplitudes via unitarity + cross terms; constants in g_k8).
__device__ float4 g_U0[NL * NQ];
__device__ float4 g_U1[NL * NQ];
__device__ float2 g_lo[2 * 256];   // lo_n[t] for layers 1,2
__device__ float4 g_k8;            // (k1, k2, k3, -) for layer-3 wire-3 fused gate

__global__ void precompute_gates(const float* __restrict__ qw) {
    __shared__ float2 s_phi2[NL * NQ];
    int id = threadIdx.x;
    if (id < NL * NQ) {
        float a = qw[3 * id + 0];
        float b = qw[3 * id + 1];
        float g = qw[3 * id + 2];
        float cA = cosf(0.5f * a), sA = sinf(0.5f * a);
        float cB = cosf(0.5f * b), sB = sinf(0.5f * b);
        float cC = cosf(0.5f * g), sC = sinf(0.5f * g);
        float m00r =  cB * cA, m00i =  sB * sA;
        float m01r = -sB * cA, m01i = -cB * sA;
        float u00r = cC * m00r + sC * m00i, u00i = cC * m00i - sC * m00r;
        float u01r = cC * m01r + sC * m01i, u01i = cC * m01i - sC * m01r;
        float mag2 = u00r * u00r + u00i * u00i;
        float inv  = rsqrtf(fmaxf(mag2, 1e-24f));
        float c  = mag2 * inv;                          // |u00|
        float br = (u01r * u00r + u01i * u00i) * inv;   // b = phi*u01
        float bi = (u01i * u00r - u01r * u00i) * inv;
        float gr = (u00r * u00r - u00i * u00i) / fmaxf(mag2, 1e-24f);  // phi^2
        float gi = (-2.f * u00r * u00i) / fmaxf(mag2, 1e-24f);
        float er = -(gr * br + gi * bi);
        float ei = -(gi * br - gr * bi);
        float dr = gr * c;
        float di = gi * c;
        g_U0[id] = make_float4(c, br, bi, 0.f);
        g_U1[id] = make_float4(er, ei, dr, di);
        s_phi2[id] = make_float2(gr, gi);
        if (id == 3 * NQ + 3) {   // layer 3, wire 3: fused-epilogue constants
            float k1 = c * c - (br * br + bi * bi);
            g_k8 = make_float4(k1, 4.f * c * br, -4.f * c * bi, 0.f);
        }
    }
    __syncthreads();
    // lo_n[t] = prod over set bits p (0..7) of t of phi^2 of (layer n, wire 11-p)
    int t = threadIdx.x;  // 0..255
    #pragma unroll
    for (int n = 1; n <= 2; n++) {
        float2 lo = make_float2(1.f, 0.f);
        #pragma unroll
        for (int p = 0; p < 8; p++)
            if ((t >> p) & 1) lo = cmul(lo, s_phi2[n * NQ + (11 - p)]);
        g_lo[(n - 1) * 256 + t] = lo;
    }
}

// phys address (element index) of logical amp under layout "active = {8..11}"
__device__ __forceinline__ int physHIGH(int x) {
    return ((x & 0xFF) << 4) | (((x >> 8) ^ x) & 15);
}

// 12-FFMA gate: M'' = [[c, b], [-conj(b), c]], u0 = (c, br, bi, -)
#define APPLY_G12(bb, u0) do {                                               \
    _Pragma("unroll")                                                        \
    for (int m = 0; m < 8; m++) {                                            \
        const int lowm = (1 << (bb)) - 1;                                    \
        const int i0 = ((m & ~lowm) << 1) | (m & lowm);                      \
        const int i1 = i0 | (1 << (bb));                                     \
        float2 v0 = r[i0], v1 = r[i1];                                       \
        float2 n0, n1;                                                       \
        n0.x = u0.x*v0.x + u0.y*v1.x - u0.z*v1.y;                            \
        n0.y = u0.x*v0.y + u0.y*v1.y + u0.z*v1.x;                            \
        n1.x = u0.x*v1.x - u0.y*v0.x - u0.z*v0.y;                            \
        n1.y = u0.x*v1.y - u0.y*v0.y + u0.z*v0.x;                            \
        r[i0] = n0; r[i1] = n1;                                              \
    }                                                                        \
} while (0)

// 14-FFMA gate (diagonal folded): u0 = (c, br, bi, -), u1 = (er, ei, dr, di)
#define APPLY_G14(bb, u0, u1) do {                                           \
    _Pragma("unroll")                                                        \
    for (int m = 0; m < 8; m++) {                                            \
        const int lowm = (1 << (bb)) - 1;                                    \
        const int i0 = ((m & ~lowm) << 1) | (m & lowm);                      \
        const int i1 = i0 | (1 << (bb));                                     \
        float2 v0 = r[i0], v1 = r[i1];                                       \
        float2 n0, n1;                                                       \
        n0.x = u0.x*v0.x + u0.y*v1.x - u0.z*v1.y;                            \
        n0.y = u0.x*v0.y + u0.y*v1.y + u0.z*v1.x;                            \
        n1.x = u1.x*v0.x - u1.y*v0.y + u1.z*v1.x - u1.w*v1.y;                \
        n1.y = u1.x*v0.y + u1.y*v0.x + u1.z*v1.y + u1.w*v1.x;                \
        r[i0] = n0; r[i1] = n1;                                              \
    }                                                                        \
} while (0)

// 16-FFMA general gate: complex 2x2 rows (m00, m01) / (m10, m11)
#define APPLY_G16(bb, m00, m01, m10, m11) do {                               \
    _Pragma("unroll")                                                        \
    for (int m = 0; m < 8; m++) {                                            \
        const int lowm = (1 << (bb)) - 1;                                    \
        const int i0 = ((m & ~lowm) << 1) | (m & lowm);                      \
        const int i1 = i0 | (1 << (bb));                                     \
        float2 v0 = r[i0], v1 = r[i1];                                       \
        float2 n0, n1;                                                       \
        n0.x = m00.x*v0.x - m00.y*v0.y + m01.x*v1.x - m01.y*v1.y;            \
        n0.y = m00.x*v0.y + m00.y*v0.x + m01.x*v1.y + m01.y*v1.x;            \
        n1.x = m10.x*v0.x - m10.y*v0.y + m11.x*v1.x - m11.y*v1.y;            \
        n1.y = m10.x*v0.y + m10.y*v0.x + m11.x*v1.y + m11.y*v1.x;            \
        r[i0] = n0; r[i1] = n1;                                              \
    }                                                                        \
} while (0)

__global__ __launch_bounds__(TPB, 3) void qsim(const float* __restrict__ x,
                                               const float* __restrict__ dw,
                                               const float* __restrict__ db,
                                               float* __restrict__ out) {
    __shared__ float2 s_psi[DIM];          // 32 KB state (swizzled layouts)
    __shared__ float4 s_U0[NL * NQ];       // row0 coefficients (c, br, bi)
    __shared__ float4 s_U1[NL * NQ];       // row1 coefficients (14-form)
    __shared__ float2 s_lo[2 * 256];       // deferred-diagonal tables, layers 1,2
    __shared__ float  s_x[NQ];
    __shared__ float2 s_w[NQ][2];          // per-BIT-POSITION local 2-vectors (layer 0 folded)
    __shared__ float  s_scalar[2];
    __shared__ float  s_z[TPB * 13];       // per-thread z values (pad 13: conflict-free)
    __shared__ float  s_p[12 * 17];        // stage-B partials (12 wires x 16 groups, pad 17)
    __shared__ float  s_q[NQ];

    const int t = threadIdx.x;
    const int bidx = blockIdx.x;

    for (int i = t; i < NL * NQ; i += TPB) { s_U0[i] = g_U0[i]; s_U1[i] = g_U1[i]; }
    #pragma unroll
    for (int i = 0; i < 2; i++) s_lo[i * 256 + t] = g_lo[i * 256 + t];
    if (t < NQ) s_x[t] = x[bidx * NQ + t];
    __syncthreads();

    if (t == 0) {
        float ss = 0.f, ma = 0.f;
        #pragma unroll
        for (int w = 0; w < NQ; w++) {
            float v = s_x[w];
            ss += v * v;
            ma = fmaxf(ma, fabsf(v));
        }
        float rr = rsqrtf(fmaxf(ss, 1e-12f));
        s_scalar[0] = rr;
        s_scalar[1] = ma * rr;
    }
    __syncthreads();
    if (t < NQ) {
        float rr = s_scalar[0], m = s_scalar[1];
        float ang = 3.14159265358979f * (s_x[t] * rr) / (m + 1e-8f);
        float c = cosf(0.5f * ang);
        float s = sinf(0.5f * ang);
        // fuse layer-0 (phase-normalized, 14-form) gate for wire t into local 2-vector
        float4 u0 = s_U0[t];
        float4 u1 = s_U1[t];
        int p = 11 - t;                    // wire t lives at bit position 11-t
        s_w[p][0] = make_float2(u0.x * c + u0.y * s, u0.z * s);
        s_w[p][1] = make_float2(u1.x * c + u1.z * s, u1.y * c + u1.w * s);
    }
    __syncthreads();

    float2 r[16];                          // 16 amps per thread (register tile)
    const int storeBase = (t << 4) | (t & 15);   // universal store: addr = storeBase ^ s

    // ---------- init in HIGH ownership: L = (s<<8)|t, amp = prod of w[bit]
    {
        float2 ct = s_w[0][t & 1];
        #pragma unroll
        for (int p = 1; p < 8; p++) ct = cmul(ct, s_w[p][(t >> p) & 1]);
        float2 m01[4], m23[4], ctm[4];
        #pragma unroll
        for (int a = 0; a < 4; a++) {
            m01[a] = cmul(s_w[8][a & 1],  s_w[9][(a >> 1) & 1]);
            m23[a] = cmul(s_w[10][a & 1], s_w[11][(a >> 1) & 1]);
        }
        #pragma unroll
        for (int a = 0; a < 4; a++) ctm[a] = cmul(ct, m01[a]);
        #pragma unroll
        for (int s = 0; s < 16; s++) r[s] = cmul(ctm[s & 3], m23[s >> 2]);
        #pragma unroll
        for (int s = 0; s < 16; s++) s_psi[storeBase ^ s] = r[s];
    }
    __syncthreads();

    #pragma unroll 1
    for (int layer = 1; layer < NL; layer++) {
        // ---------- pass MID: active positions {4..7}; load HIGH layout w/ CNOT perm folded
        {
            int T  = ((t & 0xF0) << 4) | (t & 15);
            int Xt = T ^ (T >> 1) ^ ((t & 1) ? 0xC00 : 0);
            int base = physHIGH(Xt & 0xFFF);
            #pragma unroll
            for (int s = 0; s < 16; s++) {
                int Xs = ((s << 4) ^ (s << 3)) & 0xFFF;
                r[s] = s_psi[base ^ physHIGH(Xs)];
            }
        }
        {
            const float4 p4 = s_U0[layer * NQ + 7];
            APPLY_G12(0, p4);   // position 4 = wire 7
            const float4 p5 = s_U0[layer * NQ + 6];
            APPLY_G12(1, p5);   // position 5 = wire 6
            const float4 p6 = s_U0[layer * NQ + 5];
            APPLY_G12(2, p6);   // position 6 = wire 5
            const float4 p7 = s_U0[layer * NQ + 4];
            APPLY_G12(3, p7);   // position 7 = wire 4
        }
        __syncthreads();               // all loads done before stores clobber
        #pragma unroll
        for (int s = 0; s < 16; s++) s_psi[storeBase ^ s] = r[s];
        __syncthreads();

        // ---------- pass LOW: active {0..3}; load from MID layout; 12-form gates
        {
            int base = ((t & 0xF0) << 4) | (t & 15);
            #pragma unroll
            for (int s = 0; s < 16; s++) r[s] = s_psi[base ^ ((s << 4) | s)];
        }
        {
            const float4 p0 = s_U0[layer * NQ + 11];
            APPLY_G12(0, p0);   // position 0 = wire 11
            const float4 p1 = s_U0[layer * NQ + 10];
            APPLY_G12(1, p1);
            const float4 p2 = s_U0[layer * NQ + 9];
            APPLY_G12(2, p2);
            const float4 p3 = s_U0[layer * NQ + 8];
            APPLY_G12(3, p3);
        }
        __syncthreads();
        #pragma unroll
        for (int s = 0; s < 16; s++) s_psi[storeBase ^ s] = r[s];
        __syncthreads();

        // ---------- pass HIGH: active {8..11}; load from LOW layout
        {
            int base = t ^ ((t >> 4) & 15);
            #pragma unroll
            for (int s = 0; s < 16; s++) r[s] = s_psi[base ^ (s << 8)];
        }
        if (layer < NL - 1) {
            // position-8 gate: 16-form with the deferred MID/LOW diagonal (lo)
            // premultiplied into its coefficients (scalar commutes with layer gates)
            {
                float2 lo = s_lo[(layer - 1) * 256 + t];
                float4 u0 = s_U0[layer * NQ + 3];
                float4 u1 = s_U1[layer * NQ + 3];
                float2 m00 = make_float2(lo.x * u0.x, lo.y * u0.x);      // lo * c (c real)
                float2 m01 = cmul(lo, make_float2(u0.y, u0.z));          // lo * b
                float2 m10 = cmul(lo, make_float2(u1.x, u1.y));          // lo * e
                float2 m11 = cmul(lo, make_float2(u1.z, u1.w));          // lo * d
                APPLY_G16(0, m00, m01, m10, m11);   // position 8 = wire 3
            }
            {
                const float4 p90 = s_U0[layer * NQ + 2], p91 = s_U1[layer * NQ + 2];
                APPLY_G14(1, p90, p91);
                const float4 pa0 = s_U0[layer * NQ + 1], pa1 = s_U1[layer * NQ + 1];
                APPLY_G14(2, pa0, pa1);
                const float4 pb0 = s_U0[layer * NQ + 0], pb1 = s_U1[layer * NQ + 0];
                APPLY_G14(3, pb0, pb1);
            }
            __syncthreads();
            #pragma unroll
            for (int s = 0; s < 16; s++) s_psi[storeBase ^ s] = r[s];
            __syncthreads();
        } else {
            // last layer: phases dead -> 12-form for s-bits 1..3; the s-bit-0
            // (position 8 = wire 3) gate is FUSED into the epilogue below.
            const float4 p9 = s_U0[layer * NQ + 2];
            APPLY_G12(1, p9);   // position 9 = wire 2
            const float4 pa = s_U0[layer * NQ + 1];
            APPLY_G12(2, pa);   // position 10 = wire 1
            const float4 pb = s_U0[layer * NQ + 0];
            APPLY_G12(3, pb);   // position 11 = wire 0
        }
        // layer-boundary CNOT ring folds into next MID load / epilogue index map
    }

    // ---------- epilogue: fused final gate + Walsh-transform signed sums.
    // r holds HIGH ownership pre-position-8-gate. For pairs (2u, 2u+1):
    //   P[u] = |n0|^2 + |n1|^2 = |v0|^2 + |v1|^2           (unitarity)
    //   M[u] = |n0|^2 - |n1|^2 = k1(|v0|^2-|v1|^2) + k2*A + k3*B
    //   A = v1.v0 (dot), B = v1 x v0 (cross)
    // masks: p=11 -> 7, p=10 -> 12, p=9 -> 14, p<=8 -> 15.
    float4 k8 = g_k8;
    float P[8], M[8];
    #pragma unroll
    for (int u = 0; u < 8; u++) {
        float2 v0 = r[2 * u], v1 = r[2 * u + 1];
        float a0 = v0.x * v0.x + v0.y * v0.y;
        float a1 = v1.x * v1.x + v1.y * v1.y;
        float A  = v1.x * v0.x + v1.y * v0.y;
        float B  = v1.y * v0.x - v1.x * v0.y;
        P[u] = a0 + a1;
        M[u] = k8.x * (a0 - a1) + k8.y * A + k8.z * B;
    }
    float W15 = 0.f, W14 = 0.f, W12 = 0.f, W7 = 0.f;
    #pragma unroll
    for (int u = 0; u < 8; u++) {
        if (__popc(u) & 1)        { W15 -= M[u]; W14 -= P[u]; }
        else                      { W15 += M[u]; W14 += P[u]; }
        if (__popc(u >> 1) & 1)   W12 -= P[u]; else W12 += P[u];
        if (__popc(u & 3) & 1)    W7  -= M[u]; else W7  += M[u];
    }

    int xt = t ^ ((__popc(t) & 1) ? 0xC00 : 0);
    xt ^= xt >> 1; xt ^= xt >> 2; xt ^= xt >> 4; xt ^= xt >> 8;

    // per-thread signed z values -> smem tree reduction
    #pragma unroll
    for (int w = 0; w < NQ; w++) {
        const int p = 11 - w;
        float Wv = (p == 11) ? W7 : (p == 10) ? W12 : (p == 9) ? W14 : W15;
        s_z[t * 13 + w] = ((xt >> p) & 1) ? -Wv : Wv;
    }
    __syncthreads();

    // stage B: 192 threads; thread (w + 12g) sums 16 rows for wire w
    if (t < 192) {
        int w = t % 12, g = t / 12;
        float acc = 0.f;
        #pragma unroll
        for (int k = 0; k < 16; k++) acc += s_z[(g * 16 + k) * 13 + w];
        s_p[w * 17 + g] = acc;
    }
    __syncthreads();

    // stage C: 12 threads finish the per-wire sums
    if (t < NQ) {
        float qv = 0.f;
        #pragma unroll
        for (int g = 0; g < 16; g++) qv += s_p[t * 17 + g];
        s_q[t] = qv;
    }
    __syncthreads();
    if (t < NQ) {
        float acc = db[t];
        #pragma unroll
        for (int w = 0; w < NQ; w++) acc += s_q[w] * dw[w * NQ + t];
        out[bidx * NQ + t] = tanhf(acc);
    }
}

extern "C" void kernel_launch(void* const* d_in, const int* in_sizes, int n_in,
                              void* d_out, int out_size) {
    const float* x  = (const float*)d_in[0];
    const float* qw = (const float*)d_in[1];
    const float* dw = (const float*)d_in[2];
    const float* db = (const float*)d_in[3];
    float* out = (float*)d_out;

    int batch = in_sizes[0] / NQ;

    precompute_gates<<<1, 256>>>(qw);
    qsim<<<batch, TPB>>>(x, dw, db, out);
}

// round 17
// speedup vs baseline: 1.0817x; 1.0817x over previous
#include <cuda_runtime.h>
#include <math.h>

#define NQ   12
#define DIM  4096
#define NL   4
#define TPB  256

__device__ __forceinline__ float2 cmul(float2 a, float2 b) {
    return make_float2(a.x * b.x - a.y * b.y, a.x * b.y + a.y * b.x);
}

// Phase-normalized fused RZ*RY*RX gate per (layer, wire): M = phi*U,
// phi = conj(u00)/|u00|, U in SU(2). M = diag(1, phi^2) * M'' with
// M'' = [[c, b], [-conj(b), c]], c real (12-FFMA form). Deferred diagonals:
// folded into 14-form (HIGH gates, layers 1-2), accumulated into per-thread
// lo_n[t] (MID/LOW wires, layers 1-2) folded into the position-8 HIGH gate
// (16-FFMA form), or dropped (layer 3: dead phases). The layer-3 wire-3 gate
// is fused into the epilogue quadratic form; its constants (k1,k2,k3) ride in
// g_U1[3*NQ+3] (a slot layer 3 never reads) so the epilogue gets them via the
// EXISTING shared-memory table copy (uniform LDS), not a cold global LDG.
__device__ float4 g_U0[NL * NQ];
__device__ float4 g_U1[NL * NQ];
__device__ float2 g_lo[2 * 256];   // lo_n[t] for layers 1,2

__global__ void precompute_gates(const float* __restrict__ qw) {
    __shared__ float2 s_phi2[NL * NQ];
    int id = threadIdx.x;
    if (id < NL * NQ) {
        float a = qw[3 * id + 0];
        float b = qw[3 * id + 1];
        float g = qw[3 * id + 2];
        float cA = cosf(0.5f * a), sA = sinf(0.5f * a);
        float cB = cosf(0.5f * b), sB = sinf(0.5f * b);
        float cC = cosf(0.5f * g), sC = sinf(0.5f * g);
        float m00r =  cB * cA, m00i =  sB * sA;
        float m01r = -sB * cA, m01i = -cB * sA;
        float u00r = cC * m00r + sC * m00i, u00i = cC * m00i - sC * m00r;
        float u01r = cC * m01r + sC * m01i, u01i = cC * m01i - sC * m01r;
        float mag2 = u00r * u00r + u00i * u00i;
        float inv  = rsqrtf(fmaxf(mag2, 1e-24f));
        float c  = mag2 * inv;                          // |u00|
        float br = (u01r * u00r + u01i * u00i) * inv;   // b = phi*u01
        float bi = (u01i * u00r - u01r * u00i) * inv;
        float gr = (u00r * u00r - u00i * u00i) / fmaxf(mag2, 1e-24f);  // phi^2
        float gi = (-2.f * u00r * u00i) / fmaxf(mag2, 1e-24f);
        float er = -(gr * br + gi * bi);
        float ei = -(gi * br - gr * bi);
        float dr = gr * c;
        float di = gi * c;
        g_U0[id] = make_float4(c, br, bi, 0.f);
        if (id == 3 * NQ + 3) {
            // layer-3 wire-3 gate fused into epilogue: store (k1, k2, k3)
            float k1 = c * c - (br * br + bi * bi);
            g_U1[id] = make_float4(k1, 4.f * c * br, -4.f * c * bi, 0.f);
        } else {
            g_U1[id] = make_float4(er, ei, dr, di);
        }
        s_phi2[id] = make_float2(gr, gi);
    }
    __syncthreads();
    // lo_n[t] = prod over set bits p (0..7) of t of phi^2 of (layer n, wire 11-p)
    int t = threadIdx.x;  // 0..255
    #pragma unroll
    for (int n = 1; n <= 2; n++) {
        float2 lo = make_float2(1.f, 0.f);
        #pragma unroll
        for (int p = 0; p < 8; p++)
            if ((t >> p) & 1) lo = cmul(lo, s_phi2[n * NQ + (11 - p)]);
        g_lo[(n - 1) * 256 + t] = lo;
    }
}

// phys address (element index) of logical amp under layout "active = {8..11}"
__device__ __forceinline__ int physHIGH(int x) {
    return ((x & 0xFF) << 4) | (((x >> 8) ^ x) & 15);
}

// 12-FFMA gate: M'' = [[c, b], [-conj(b), c]], u0 = (c, br, bi, -)
#define APPLY_G12(bb, u0) do {                                               \
    _Pragma("unroll")                                                        \
    for (int m = 0; m < 8; m++) {                                            \
        const int lowm = (1 << (bb)) - 1;                                    \
        const int i0 = ((m & ~lowm) << 1) | (m & lowm);                      \
        const int i1 = i0 | (1 << (bb));                                     \
        float2 v0 = r[i0], v1 = r[i1];                                       \
        float2 n0, n1;                                                       \
        n0.x = u0.x*v0.x + u0.y*v1.x - u0.z*v1.y;                            \
        n0.y = u0.x*v0.y + u0.y*v1.y + u0.z*v1.x;                            \
        n1.x = u0.x*v1.x - u0.y*v0.x - u0.z*v0.y;                            \
        n1.y = u0.x*v1.y - u0.y*v0.y + u0.z*v0.x;                            \
        r[i0] = n0; r[i1] = n1;                                              \
    }                                                                        \
} while (0)

// 14-FFMA gate (diagonal folded): u0 = (c, br, bi, -), u1 = (er, ei, dr, di)
#define APPLY_G14(bb, u0, u1) do {                                           \
    _Pragma("unroll")                                                        \
    for (int m = 0; m < 8; m++) {                                            \
        const int lowm = (1 << (bb)) - 1;                                    \
        const int i0 = ((m & ~lowm) << 1) | (m & lowm);                      \
        const int i1 = i0 | (1 << (bb));                                     \
        float2 v0 = r[i0], v1 = r[i1];                                       \
        float2 n0, n1;                                                       \
        n0.x = u0.x*v0.x + u0.y*v1.x - u0.z*v1.y;                            \
        n0.y = u0.x*v0.y + u0.y*v1.y + u0.z*v1.x;                            \
        n1.x = u1.x*v0.x - u1.y*v0.y + u1.z*v1.x - u1.w*v1.y;                \
        n1.y = u1.x*v0.y + u1.y*v0.x + u1.z*v1.y + u1.w*v1.x;                \
        r[i0] = n0; r[i1] = n1;                                              \
    }                                                                        \
} while (0)

// 16-FFMA general gate: complex 2x2 rows (m00, m01) / (m10, m11)
#define APPLY_G16(bb, m00, m01, m10, m11) do {                               \
    _Pragma("unroll")                                                        \
    for (int m = 0; m < 8; m++) {                                            \
        const int lowm = (1 << (bb)) - 1;                                    \
        const int i0 = ((m & ~lowm) << 1) | (m & lowm);                      \
        const int i1 = i0 | (1 << (bb));                                     \
        float2 v0 = r[i0], v1 = r[i1];                                       \
        float2 n0, n1;                                                       \
        n0.x = m00.x*v0.x - m00.y*v0.y + m01.x*v1.x - m01.y*v1.y;            \
        n0.y = m00.x*v0.y + m00.y*v0.x + m01.x*v1.y + m01.y*v1.x;            \
        n1.x = m10.x*v0.x - m10.y*v0.y + m11.x*v1.x - m11.y*v1.y;            \
        n1.y = m10.x*v0.y + m10.y*v0.x + m11.x*v1.y + m11.y*v1.x;            \
        r[i0] = n0; r[i1] = n1;                                              \
    }                                                                        \
} while (0)

__global__ __launch_bounds__(TPB, 3) void qsim(const float* __restrict__ x,
                                               const float* __restrict__ dw,
                                               const float* __restrict__ db,
                                               float* __restrict__ out) {
    __shared__ float2 s_psi[DIM];          // 32 KB state (swizzled layouts)
    __shared__ float4 s_U0[NL * NQ];       // row0 coefficients (c, br, bi)
    __shared__ float4 s_U1[NL * NQ];       // row1 coefficients (14-form) + k8 slot
    __shared__ float2 s_lo[2 * 256];       // deferred-diagonal tables, layers 1,2
    __shared__ float  s_x[NQ];
    __shared__ float2 s_w[NQ][2];          // per-BIT-POSITION local 2-vectors (layer 0 folded)
    __shared__ float  s_scalar[2];
    __shared__ float  s_z[TPB * 13];       // per-thread z values (pad 13: conflict-free)
    __shared__ float  s_p[12 * 17];        // stage-B partials (12 wires x 16 groups, pad 17)
    __shared__ float  s_q[NQ];

    const int t = threadIdx.x;
    const int bidx = blockIdx.x;

    for (int i = t; i < NL * NQ; i += TPB) { s_U0[i] = g_U0[i]; s_U1[i] = g_U1[i]; }
    #pragma unroll
    for (int i = 0; i < 2; i++) s_lo[i * 256 + t] = g_lo[i * 256 + t];
    if (t < NQ) s_x[t] = x[bidx * NQ + t];
    __syncthreads();

    if (t == 0) {
        float ss = 0.f, ma = 0.f;
        #pragma unroll
        for (int w = 0; w < NQ; w++) {
            float v = s_x[w];
            ss += v * v;
            ma = fmaxf(ma, fabsf(v));
        }
        float rr = rsqrtf(fmaxf(ss, 1e-12f));
        s_scalar[0] = rr;
        s_scalar[1] = ma * rr;
    }
    __syncthreads();
    if (t < NQ) {
        float rr = s_scalar[0], m = s_scalar[1];
        float ang = 3.14159265358979f * (s_x[t] * rr) / (m + 1e-8f);
        float c = cosf(0.5f * ang);
        float s = sinf(0.5f * ang);
        // fuse layer-0 (phase-normalized, 14-form) gate for wire t into local 2-vector
        float4 u0 = s_U0[t];
        float4 u1 = s_U1[t];
        int p = 11 - t;                    // wire t lives at bit position 11-t
        s_w[p][0] = make_float2(u0.x * c + u0.y * s, u0.z * s);
        s_w[p][1] = make_float2(u1.x * c + u1.z * s, u1.y * c + u1.w * s);
    }
    __syncthreads();

    float2 r[16];                          // 16 amps per thread (register tile)
    const int storeBase = (t << 4) | (t & 15);   // universal store: addr = storeBase ^ s

    // ---------- init in HIGH ownership: L = (s<<8)|t, amp = prod of w[bit]
    {
        float2 ct = s_w[0][t & 1];
        #pragma unroll
        for (int p = 1; p < 8; p++) ct = cmul(ct, s_w[p][(t >> p) & 1]);
        float2 m01[4], m23[4], ctm[4];
        #pragma unroll
        for (int a = 0; a < 4; a++) {
            m01[a] = cmul(s_w[8][a & 1],  s_w[9][(a >> 1) & 1]);
            m23[a] = cmul(s_w[10][a & 1], s_w[11][(a >> 1) & 1]);
        }
        #pragma unroll
        for (int a = 0; a < 4; a++) ctm[a] = cmul(ct, m01[a]);
        #pragma unroll
        for (int s = 0; s < 16; s++) r[s] = cmul(ctm[s & 3], m23[s >> 2]);
        #pragma unroll
        for (int s = 0; s < 16; s++) s_psi[storeBase ^ s] = r[s];
    }
    __syncthreads();

    #pragma unroll 1
    for (int layer = 1; layer < NL; layer++) {
        // ---------- pass MID: active positions {4..7}; load HIGH layout w/ CNOT perm folded
        {
            int T  = ((t & 0xF0) << 4) | (t & 15);
            int Xt = T ^ (T >> 1) ^ ((t & 1) ? 0xC00 : 0);
            int base = physHIGH(Xt & 0xFFF);
            #pragma unroll
            for (int s = 0; s < 16; s++) {
                int Xs = ((s << 4) ^ (s << 3)) & 0xFFF;
                r[s] = s_psi[base ^ physHIGH(Xs)];
            }
        }
        {
            const float4 p4 = s_U0[layer * NQ + 7];
            APPLY_G12(0, p4);   // position 4 = wire 7
            const float4 p5 = s_U0[layer * NQ + 6];
            APPLY_G12(1, p5);   // position 5 = wire 6
            const float4 p6 = s_U0[layer * NQ + 5];
            APPLY_G12(2, p6);   // position 6 = wire 5
            const float4 p7 = s_U0[layer * NQ + 4];
            APPLY_G12(3, p7);   // position 7 = wire 4
        }
        __syncthreads();               // all loads done before stores clobber
        #pragma unroll
        for (int s = 0; s < 16; s++) s_psi[storeBase ^ s] = r[s];
        __syncthreads();

        // ---------- pass LOW: active {0..3}; load from MID layout; 12-form gates
        {
            int base = ((t & 0xF0) << 4) | (t & 15);
            #pragma unroll
            for (int s = 0; s < 16; s++) r[s] = s_psi[base ^ ((s << 4) | s)];
        }
        {
            const float4 p0 = s_U0[layer * NQ + 11];
            APPLY_G12(0, p0);   // position 0 = wire 11
            const float4 p1 = s_U0[layer * NQ + 10];
            APPLY_G12(1, p1);
            const float4 p2 = s_U0[layer * NQ + 9];
            APPLY_G12(2, p2);
            const float4 p3 = s_U0[layer * NQ + 8];
            APPLY_G12(3, p3);
        }
        __syncthreads();
        #pragma unroll
        for (int s = 0; s < 16; s++) s_psi[storeBase ^ s] = r[s];
        __syncthreads();

        // ---------- pass HIGH: active {8..11}; load from LOW layout
        {
            int base = t ^ ((t >> 4) & 15);
            #pragma unroll
            for (int s = 0; s < 16; s++) r[s] = s_psi[base ^ (s << 8)];
        }
        if (layer < NL - 1) {
            // position-8 gate: 16-form with the deferred MID/LOW diagonal (lo)
            // premultiplied into its coefficients (scalar commutes with layer gates)
            {
                float2 lo = s_lo[(layer - 1) * 256 + t];
                float4 u0 = s_U0[layer * NQ + 3];
                float4 u1 = s_U1[layer * NQ + 3];
                float2 m00 = make_float2(lo.x * u0.x, lo.y * u0.x);      // lo * c (c real)
                float2 m01 = cmul(lo, make_float2(u0.y, u0.z));          // lo * b
                float2 m10 = cmul(lo, make_float2(u1.x, u1.y));          // lo * e
                float2 m11 = cmul(lo, make_float2(u1.z, u1.w));          // lo * d
                APPLY_G16(0, m00, m01, m10, m11);   // position 8 = wire 3
            }
            {
                const float4 p90 = s_U0[layer * NQ + 2], p91 = s_U1[layer * NQ + 2];
                APPLY_G14(1, p90, p91);
                const float4 pa0 = s_U0[layer * NQ + 1], pa1 = s_U1[layer * NQ + 1];
                APPLY_G14(2, pa0, pa1);
                const float4 pb0 = s_U0[layer * NQ + 0], pb1 = s_U1[layer * NQ + 0];
                APPLY_G14(3, pb0, pb1);
            }
            __syncthreads();
            #pragma unroll
            for (int s = 0; s < 16; s++) s_psi[storeBase ^ s] = r[s];
            __syncthreads();
        } else {
            // last layer: phases dead -> 12-form for s-bits 1..3; the s-bit-0
            // (position 8 = wire 3) gate is FUSED into the epilogue below.
            const float4 p9 = s_U0[layer * NQ + 2];
            APPLY_G12(1, p9);   // position 9 = wire 2
            const float4 pa = s_U0[layer * NQ + 1];
            APPLY_G12(2, pa);   // position 10 = wire 1
            const float4 pb = s_U0[layer * NQ + 0];
            APPLY_G12(3, pb);   // position 11 = wire 0
        }
        // layer-boundary CNOT ring folds into next MID load / epilogue index map
    }

    // ---------- epilogue: fused final gate + Walsh-transform signed sums.
    // r holds HIGH ownership pre-position-8-gate. For pairs (2u, 2u+1):
    //   P[u] = |n0|^2 + |n1|^2 = |v0|^2 + |v1|^2           (unitarity)
    //   M[u] = |n0|^2 - |n1|^2 = k1(|v0|^2-|v1|^2) + k2*A + k3*B
    //   A = v1.v0 (dot), B = v1 x v0 (cross)
    // k8 = (k1,k2,k3) arrives via shared gate table (uniform LDS, no cold LDG).
    // masks: p=11 -> 7, p=10 -> 12, p=9 -> 14, p<=8 -> 15.
    float4 k8 = s_U1[3 * NQ + 3];
    float P[8], M[8];
    #pragma unroll
    for (int u = 0; u < 8; u++) {
        float2 v0 = r[2 * u], v1 = r[2 * u + 1];
        float a0 = v0.x * v0.x + v0.y * v0.y;
        float a1 = v1.x * v1.x + v1.y * v1.y;
        float A  = v1.x * v0.x + v1.y * v0.y;
        float B  = v1.y * v0.x - v1.x * v0.y;
        P[u] = a0 + a1;
        M[u] = k8.x * (a0 - a1) + k8.y * A + k8.z * B;
    }
    float W15 = 0.f, W14 = 0.f, W12 = 0.f, W7 = 0.f;
    #pragma unroll
    for (int u = 0; u < 8; u++) {
        if (__popc(u) & 1)        { W15 -= M[u]; W14 -= P[u]; }
        else                      { W15 += M[u]; W14 += P[u]; }
        if (__popc(u >> 1) & 1)   W12 -= P[u]; else W12 += P[u];
        if (__popc(u & 3) & 1)    W7  -= M[u]; else W7  += M[u];
    }

    int xt = t ^ ((__popc(t) & 1) ? 0xC00 : 0);
    xt ^= xt >> 1; xt ^= xt >> 2; xt ^= xt >> 4; xt ^= xt >> 8;

    // per-thread signed z values -> smem tree reduction
    #pragma unroll
    for (int w = 0; w < NQ; w++) {
        const int p = 11 - w;
        float Wv = (p == 11) ? W7 : (p == 10) ? W12 : (p == 9) ? W14 : W15;
        s_z[t * 13 + w] = ((xt >> p) & 1) ? -Wv : Wv;
    }
    __syncthreads();

    // stage B: 192 threads; thread (w + 12g) sums 16 rows for wire w
    if (t < 192) {
        int w = t % 12, g = t / 12;
        float acc = 0.f;
        #pragma unroll
        for (int k = 0; k < 16; k++) acc += s_z[(g * 16 + k) * 13 + w];
        s_p[w * 17 + g] = acc;
    }
    __syncthreads();

    // stage C: 12 threads finish the per-wire sums
    if (t < NQ) {
        float qv = 0.f;
        #pragma unroll
        for (int g = 0; g < 16; g++) qv += s_p[t * 17 + g];
        s_q[t] = qv;
    }
    __syncthreads();
    if (t < NQ) {
        float acc = db[t];
        #pragma unroll
        for (int w = 0; w < NQ; w++) acc += s_q[w] * dw[w * NQ + t];
        out[bidx * NQ + t] = tanhf(acc);
    }
}

extern "C" void kernel_launch(void* const* d_in, const int* in_sizes, int n_in,
                              void* d_out, int out_size) {
    const float* x  = (const float*)d_in[0];
    const float* qw = (const float*)d_in[1];
    const float* dw = (const float*)d_in[2];
    const float* db = (const float*)d_in[3];
    float* out = (float*)d_out;

    int batch = in_sizes[0] / NQ;

    precompute_gates<<<1, 256>>>(qw);
    qsim<<<batch, TPB>>>(x, dw, db, out);
}